// round 4
// baseline (speedup 1.0000x reference)
#include <cuda_runtime.h>
#include <cuda_fp16.h>
#include <math.h>
#include <stdint.h>

#define F 128
#define MAXN 50000
#define MAXEGO 1250000
#define MAXE 700000

// fp32 scratch
__device__ float g_bufA[MAXN * F];
__device__ float g_bufB[MAXN * F];
// fp16 activation shadows
__device__ __half g_xb[MAXN * F];
__device__ __half g_yb0[MAXN * F];
__device__ __half g_yb1[MAXN * F];
// CSR scratch
__device__ int g_degEgo[MAXN];
__device__ int g_degE[MAXN];
__device__ int g_offEgo[MAXN + 1];
__device__ int g_offE[MAXN + 1];
__device__ int g_curEgo[MAXN];
__device__ int g_curE[MAXN];
__device__ int g_adjEgo[MAXEGO];
__device__ int g_adjE[MAXE];

// ---------------------------------------------------------------------------
__global__ void f2h_kernel(const float* __restrict__ x, __half* __restrict__ y, int n4) {
    int i = blockIdx.x * blockDim.x + threadIdx.x;
    if (i >= n4) return;
    float4 v = ((const float4*)x)[i];
    __half2 h0 = __floats2half2_rn(v.x, v.y);
    __half2 h1 = __floats2half2_rn(v.z, v.w);
    uint2 u;
    u.x = *(uint32_t*)&h0; u.y = *(uint32_t*)&h1;
    ((uint2*)y)[i] = u;
}

__global__ void hist_kernel(const int* __restrict__ w, int ne, int* __restrict__ deg) {
    int i = blockIdx.x * blockDim.x + threadIdx.x;
    if (i < ne) atomicAdd(&deg[__ldg(w + i)], 1);
}

// single-block exclusive scan over n counters -> off[0..n], cur copy
__global__ void scan_kernel(const int* __restrict__ deg, int n,
                            int* __restrict__ off, int* __restrict__ cur) {
    __shared__ int wsum[32];
    int t = threadIdx.x;
    int chunk = (n + 1023) >> 10;
    int lo = t * chunk;
    int hi = min(lo + chunk, n);
    int s = 0;
    for (int i = lo; i < hi; i++) s += __ldg(deg + i);
    int lane = t & 31, wid = t >> 5;
    int v = s;
#pragma unroll
    for (int o = 1; o < 32; o <<= 1) {
        int u = __shfl_up_sync(0xffffffffu, v, o);
        if (lane >= o) v += u;
    }
    if (lane == 31) wsum[wid] = v;
    __syncthreads();
    if (wid == 0) {
        int w = wsum[lane];
#pragma unroll
        for (int o = 1; o < 32; o <<= 1) {
            int u = __shfl_up_sync(0xffffffffu, w, o);
            if (lane >= o) w += u;
        }
        wsum[lane] = w;
    }
    __syncthreads();
    int run = v - s + (wid ? wsum[wid - 1] : 0);
    for (int i = lo; i < hi; i++) {
        off[i] = run; cur[i] = run;
        run += __ldg(deg + i);
    }
    if (hi == n) off[n] = run;  // all threads past end write same total
}

__global__ void fill_kernel(const int* __restrict__ w, const int* __restrict__ r,
                            int ne, int* __restrict__ cur, int* __restrict__ adj) {
    int i = blockIdx.x * blockDim.x + threadIdx.x;
    if (i >= ne) return;
    int pos = atomicAdd(&cur[__ldg(w + i)], 1);
    adj[pos] = __ldg(r + i);
}

// ---------------------------------------------------------------------------
// segsum over CSR, fp16 source rows (128 wide) -> fp32 out. Warp per node.
__device__ __forceinline__ void addh2(float2& a, uint32_t h) {
    float2 f = __half22float2(*(__half2*)&h);
    a.x += f.x; a.y += f.y;
}
__global__ void segsum128h_kernel(const __half* __restrict__ x,
                                  const int* __restrict__ off,
                                  const int* __restrict__ adj,
                                  float* __restrict__ out, int n) {
    int gw = (blockIdx.x * blockDim.x + threadIdx.x) >> 5;
    int lane = threadIdx.x & 31;
    if (gw >= n) return;
    int s = __ldg(off + gw), e = __ldg(off + gw + 1);
    float2 acc[4] = {{0.f,0.f},{0.f,0.f},{0.f,0.f},{0.f,0.f}};
    for (int j = s; j < e; ) {
        int cnt = min(32, e - j);
        int my = (lane < cnt) ? __ldg(adj + j + lane) : 0;
        int k = 0;
        for (; k + 2 <= cnt; k += 2) {
            int r0 = __shfl_sync(0xffffffffu, my, k);
            int r1 = __shfl_sync(0xffffffffu, my, k + 1);
            uint4 u0 = __ldg((const uint4*)(x + (size_t)r0 * 128) + lane);
            uint4 u1 = __ldg((const uint4*)(x + (size_t)r1 * 128) + lane);
            addh2(acc[0], u0.x); addh2(acc[1], u0.y); addh2(acc[2], u0.z); addh2(acc[3], u0.w);
            addh2(acc[0], u1.x); addh2(acc[1], u1.y); addh2(acc[2], u1.z); addh2(acc[3], u1.w);
        }
        if (k < cnt) {
            int r0 = __shfl_sync(0xffffffffu, my, k);
            uint4 u0 = __ldg((const uint4*)(x + (size_t)r0 * 128) + lane);
            addh2(acc[0], u0.x); addh2(acc[1], u0.y); addh2(acc[2], u0.z); addh2(acc[3], u0.w);
        }
        j += cnt;
    }
    float4* op = (float4*)(out + (size_t)gw * 128 + lane * 8);
    op[0] = make_float4(acc[0].x, acc[0].y, acc[1].x, acc[1].y);
    op[1] = make_float4(acc[2].x, acc[2].y, acc[3].x, acc[3].y);
}

// segsum over CSR, fp32 source rows (64 wide) -> fp32. Warp per node.
__global__ void segsum64f_kernel(const float* __restrict__ x,
                                 const int* __restrict__ off,
                                 const int* __restrict__ adj,
                                 float* __restrict__ out, int n) {
    int gw = (blockIdx.x * blockDim.x + threadIdx.x) >> 5;
    int lane = threadIdx.x & 31;
    if (gw >= n) return;
    int s = __ldg(off + gw), e = __ldg(off + gw + 1);
    float2 acc = make_float2(0.f, 0.f);
    for (int j = s; j < e; ) {
        int cnt = min(32, e - j);
        int my = (lane < cnt) ? __ldg(adj + j + lane) : 0;
        int k = 0;
        for (; k + 2 <= cnt; k += 2) {
            int r0 = __shfl_sync(0xffffffffu, my, k);
            int r1 = __shfl_sync(0xffffffffu, my, k + 1);
            float2 v0 = __ldg((const float2*)(x + (size_t)r0 * 64) + lane);
            float2 v1 = __ldg((const float2*)(x + (size_t)r1 * 64) + lane);
            acc.x += v0.x + v1.x; acc.y += v0.y + v1.y;
        }
        if (k < cnt) {
            int r0 = __shfl_sync(0xffffffffu, my, k);
            float2 v0 = __ldg((const float2*)(x + (size_t)r0 * 64) + lane);
            acc.x += v0.x; acc.y += v0.y;
        }
        j += cnt;
    }
    *(float2*)(out + (size_t)gw * 64 + lane * 2) = acc;
}

// ---------------------------------------------------------------------------
// TF32 tensor-core GEMM, 64x64 tile per CTA (grid.y = col tile of 64).
// AMODE 0: A = scale * Af ; 1: A = Ah + B2f ; 2: A = Ah.
// BOUT: write fp16 (stride 128) else fp32 (stride ncstride).
__device__ __forceinline__ uint32_t f2tf32(float f) {
    uint32_t u;
    asm("cvt.rna.tf32.f32 %0, %1;" : "=r"(u) : "f"(f));
    return u;
}
__device__ __forceinline__ void mma_tf32(float& c0, float& c1, float& c2, float& c3,
                                         uint32_t a0, uint32_t a1, uint32_t a2, uint32_t a3,
                                         uint32_t b0, uint32_t b1) {
    asm volatile(
        "mma.sync.aligned.m16n8k8.row.col.f32.tf32.tf32.f32 "
        "{%0,%1,%2,%3}, {%4,%5,%6,%7}, {%8,%9}, {%0,%1,%2,%3};"
        : "+f"(c0), "+f"(c1), "+f"(c2), "+f"(c3)
        : "r"(a0), "r"(a1), "r"(a2), "r"(a3), "r"(b0), "r"(b1));
}

template <int AMODE, bool RELU, bool BIAS, bool VECW, bool BOUT>
__global__ void __launch_bounds__(256, 3)
gemm_tc_kernel(const float* __restrict__ Af, const __half* __restrict__ Ah,
               const float* __restrict__ B2f,
               const float* __restrict__ W, const float* __restrict__ bias,
               float* __restrict__ Cf, __half* __restrict__ Ch,
               int M, int nca, int ncstride, float scale) {
    constexpr int PW = 72;
    constexpr int PA = 132;

    extern __shared__ float sm[];
    uint32_t* Ws = (uint32_t*)sm;              // [128][72] tf32
    uint32_t* As = (uint32_t*)(sm + 128 * PW); // [64][132] tf32
    __shared__ float bs[64];

    const int tid  = threadIdx.x;
    const int lane = tid & 31;
    const int warp = tid >> 5;
    const int wr   = warp >> 1;
    const int wc   = warp & 1;
    const int g    = lane >> 2;
    const int t    = lane & 3;
    const int cb   = blockIdx.y * 64;

    if (VECW) {
#pragma unroll
        for (int i = tid; i < 128 * 16; i += 256) {
            int k = i >> 4, c4 = i & 15;
            float4 v = __ldg((const float4*)(W + (size_t)k * nca + cb) + c4);
            uint4 u;
            u.x = f2tf32(v.x); u.y = f2tf32(v.y); u.z = f2tf32(v.z); u.w = f2tf32(v.w);
            *(uint4*)(Ws + k * PW + c4 * 4) = u;
        }
    } else {
#pragma unroll
        for (int i = tid; i < 128 * 64; i += 256) {
            int k = i >> 6, c = i & 63;
            int gc = cb + c;
            float w = (gc < nca) ? __ldg(W + (size_t)k * nca + gc) : 0.f;
            Ws[k * PW + c] = f2tf32(w);
        }
    }
    if (BIAS && tid < 64) bs[tid] = (cb + tid < nca) ? bias[cb + tid] : 0.f;

    const int base = blockIdx.x * 64;
    if (AMODE == 0) {
#pragma unroll
        for (int i = tid; i < 64 * 32; i += 256) {
            int rr = i >> 5, c4 = i & 31;
            int row = base + rr;
            uint4 u = make_uint4(0u, 0u, 0u, 0u);
            if (row < M) {
                float4 v = ((const float4*)(Af + (size_t)row * 128))[c4];
                u.x = f2tf32(v.x * scale); u.y = f2tf32(v.y * scale);
                u.z = f2tf32(v.z * scale); u.w = f2tf32(v.w * scale);
            }
            ((uint4*)(As + rr * PA))[c4] = u;
        }
    } else {
#pragma unroll
        for (int i = tid; i < 64 * 16; i += 256) {
            int rr = i >> 4, c8 = i & 15;
            int row = base + rr;
            uint4 o0 = make_uint4(0u, 0u, 0u, 0u);
            uint4 o1 = make_uint4(0u, 0u, 0u, 0u);
            if (row < M) {
                uint4 hu = __ldg((const uint4*)(Ah + (size_t)row * 128) + c8);
                float2 f0 = __half22float2(*(__half2*)&hu.x);
                float2 f1 = __half22float2(*(__half2*)&hu.y);
                float2 f2 = __half22float2(*(__half2*)&hu.z);
                float2 f3 = __half22float2(*(__half2*)&hu.w);
                if (AMODE == 1) {
                    float4 b0 = ((const float4*)(B2f + (size_t)row * 128))[c8 * 2];
                    float4 b1 = ((const float4*)(B2f + (size_t)row * 128))[c8 * 2 + 1];
                    f0.x += b0.x; f0.y += b0.y; f1.x += b0.z; f1.y += b0.w;
                    f2.x += b1.x; f2.y += b1.y; f3.x += b1.z; f3.y += b1.w;
                }
                o0.x = f2tf32(f0.x); o0.y = f2tf32(f0.y);
                o0.z = f2tf32(f1.x); o0.w = f2tf32(f1.y);
                o1.x = f2tf32(f2.x); o1.y = f2tf32(f2.y);
                o1.z = f2tf32(f3.x); o1.w = f2tf32(f3.y);
            }
            uint4* dst = (uint4*)(As + rr * PA + c8 * 8);
            dst[0] = o0; dst[1] = o1;
        }
    }
    __syncthreads();

    float acc[4][4];
#pragma unroll
    for (int nt = 0; nt < 4; nt++)
#pragma unroll
        for (int j = 0; j < 4; j++) acc[nt][j] = 0.f;

    const int r0 = wr * 16 + g;
#pragma unroll
    for (int ks = 0; ks < 16; ks++) {
        const int k0 = ks * 8;
        uint32_t a0 = As[r0 * PA + k0 + t];
        uint32_t a1 = As[(r0 + 8) * PA + k0 + t];
        uint32_t a2 = As[r0 * PA + k0 + t + 4];
        uint32_t a3 = As[(r0 + 8) * PA + k0 + t + 4];
#pragma unroll
        for (int nt = 0; nt < 4; nt++) {
            int n = wc * 32 + nt * 8 + g;
            uint32_t b0 = Ws[(k0 + t) * PW + n];
            uint32_t b1 = Ws[(k0 + t + 4) * PW + n];
            mma_tf32(acc[nt][0], acc[nt][1], acc[nt][2], acc[nt][3],
                     a0, a1, a2, a3, b0, b1);
        }
    }

    int gr0 = base + wr * 16 + g;
    int gr1 = gr0 + 8;
#pragma unroll
    for (int nt = 0; nt < 4; nt++) {
        int col = wc * 32 + nt * 8 + t * 2;
        float bx = BIAS ? bs[col] : 0.f;
        float by = BIAS ? bs[col + 1] : 0.f;
        float2 v0 = make_float2(acc[nt][0] + bx, acc[nt][1] + by);
        float2 v1 = make_float2(acc[nt][2] + bx, acc[nt][3] + by);
        if (RELU) {
            v0.x = fmaxf(v0.x, 0.f); v0.y = fmaxf(v0.y, 0.f);
            v1.x = fmaxf(v1.x, 0.f); v1.y = fmaxf(v1.y, 0.f);
        }
        int gcol = cb + col;
        if (BOUT) {
            __half2 h0 = __floats2half2_rn(v0.x, v0.y);
            __half2 h1 = __floats2half2_rn(v1.x, v1.y);
            if (gr0 < M) *(__half2*)(Ch + (size_t)gr0 * 128 + gcol) = h0;
            if (gr1 < M) *(__half2*)(Ch + (size_t)gr1 * 128 + gcol) = h1;
        } else {
            if (gr0 < M) *(float2*)(Cf + (size_t)gr0 * ncstride + gcol) = v0;
            if (gr1 < M) *(float2*)(Cf + (size_t)gr1 * ncstride + gcol) = v1;
        }
    }
}

// ---------------------------------------------------------------------------
// out = log_softmax(y + aggr + bias) over nc=47 cols; y/aggr stride 64.
__global__ void final_logsoftmax_kernel(const float* __restrict__ y,
                                        const float* __restrict__ aggr,
                                        const float* __restrict__ bias,
                                        float* __restrict__ out, int M, int nc) {
    int warp = (blockIdx.x * blockDim.x + threadIdx.x) >> 5;
    int lane = threadIdx.x & 31;
    if (warp >= M) return;
    const float* yp = y + (size_t)warp * 64;
    const float* ap = aggr + (size_t)warp * 64;
    int c2 = lane + 32;
    float v1 = (lane < nc) ? yp[lane] + ap[lane] + __ldg(bias + lane) : -INFINITY;
    float v2 = (c2 < nc)   ? yp[c2] + ap[c2] + __ldg(bias + c2)       : -INFINITY;
    float mx = fmaxf(v1, v2);
#pragma unroll
    for (int o = 16; o; o >>= 1) mx = fmaxf(mx, __shfl_xor_sync(0xffffffffu, mx, o));
    float s = ((lane < nc) ? expf(v1 - mx) : 0.f) + ((c2 < nc) ? expf(v2 - mx) : 0.f);
#pragma unroll
    for (int o = 16; o; o >>= 1) s += __shfl_xor_sync(0xffffffffu, s, o);
    float lg = logf(s) + mx;
    float* orow = out + (size_t)warp * nc;
    if (lane < nc) orow[lane] = v1 - lg;
    if (c2 < nc)   orow[c2]   = v2 - lg;
}

// ---------------------------------------------------------------------------
extern "C" void kernel_launch(void* const* d_in, const int* in_sizes, int n_in,
                              void* d_out, int out_size) {
    const float* x_in   = (const float*)d_in[0];
    const int*   ei     = (const int*)d_in[1];
    const int*   ego    = (const int*)d_in[2];
    const float* W_ego0 = (const float*)d_in[3];
    const float* b_ego0 = (const float*)d_in[4];
    const float* W_gin0 = (const float*)d_in[5];
    const float* b_gin0 = (const float*)d_in[6];
    const float* W_ego1 = (const float*)d_in[7];
    const float* b_ego1 = (const float*)d_in[8];
    const float* W_gin1 = (const float*)d_in[9];
    const float* b_gin1 = (const float*)d_in[10];

    int N    = in_sizes[0] / F;
    int E    = in_sizes[1] / 2;
    int EGO  = in_sizes[2] / 2;
    int OUTC = in_sizes[10];
    float invN = 1.0f / (float)N;

    float *bufA, *bufB;
    __half *xb, *yb0, *yb1;
    int *degEgo, *degE, *offEgo, *offE, *curEgo, *curE, *adjEgo, *adjE;
    cudaGetSymbolAddress((void**)&bufA, g_bufA);
    cudaGetSymbolAddress((void**)&bufB, g_bufB);
    cudaGetSymbolAddress((void**)&xb, g_xb);
    cudaGetSymbolAddress((void**)&yb0, g_yb0);
    cudaGetSymbolAddress((void**)&yb1, g_yb1);
    cudaGetSymbolAddress((void**)&degEgo, g_degEgo);
    cudaGetSymbolAddress((void**)&degE, g_degE);
    cudaGetSymbolAddress((void**)&offEgo, g_offEgo);
    cudaGetSymbolAddress((void**)&offE, g_offE);
    cudaGetSymbolAddress((void**)&curEgo, g_curEgo);
    cudaGetSymbolAddress((void**)&curE, g_curE);
    cudaGetSymbolAddress((void**)&adjEgo, g_adjEgo);
    cudaGetSymbolAddress((void**)&adjE, g_adjE);

    const size_t smg = (size_t)(128 * 72 + 64 * 132) * 4;
    cudaFuncSetAttribute(gemm_tc_kernel<0, true, true, true, true>,
                         cudaFuncAttributeMaxDynamicSharedMemorySize, (int)smg);
    cudaFuncSetAttribute(gemm_tc_kernel<1, true, true, true, true>,
                         cudaFuncAttributeMaxDynamicSharedMemorySize, (int)smg);
    cudaFuncSetAttribute(gemm_tc_kernel<2, false, false, false, false>,
                         cudaFuncAttributeMaxDynamicSharedMemorySize, (int)smg);

    dim3 g128((N + 63) / 64, 2);
    dim3 g64((N + 63) / 64, 1);
    int sg = (N * 32 + 255) / 256;   // warp-per-node kernels

    // ---- CSR build (both lists) + fp16 convert ----
    cudaMemsetAsync(degEgo, 0, N * sizeof(int), 0);
    cudaMemsetAsync(degE, 0, N * sizeof(int), 0);
    f2h_kernel<<<(N * F / 4 + 255) / 256, 256>>>(x_in, xb, N * F / 4);
    hist_kernel<<<(EGO + 255) / 256, 256>>>(ego, EGO, degEgo);          // widx = ego_row
    hist_kernel<<<(E + 255) / 256, 256>>>(ei + E, E, degE);             // widx = tgt
    scan_kernel<<<1, 1024>>>(degEgo, N, offEgo, curEgo);
    scan_kernel<<<1, 1024>>>(degE, N, offE, curE);
    fill_kernel<<<(EGO + 255) / 256, 256>>>(ego, ego + EGO, EGO, curEgo, adjEgo); // ridx = ego_col
    fill_kernel<<<(E + 255) / 256, 256>>>(ei + E, ei, E, curE, adjE);             // ridx = src

    // ---- layer 0: Ego ----
    segsum128h_kernel<<<sg, 256>>>(xb, offEgo, adjEgo, bufA, N);
    gemm_tc_kernel<0, true, true, true, true><<<g128, 256, smg>>>(
        bufA, nullptr, nullptr, W_ego0, b_ego0, nullptr, yb0, N, 128, 128, invN);
    // ---- layer 0: GIN ----
    segsum128h_kernel<<<sg, 256>>>(yb0, offE, adjE, bufB, N);
    gemm_tc_kernel<1, true, true, true, true><<<g128, 256, smg>>>(
        nullptr, yb0, bufB, W_gin0, b_gin0, nullptr, yb1, N, 128, 128, 1.0f);
    // ---- layer 1: Ego ----
    segsum128h_kernel<<<sg, 256>>>(yb1, offEgo, adjEgo, bufA, N);
    gemm_tc_kernel<0, true, true, true, true><<<g128, 256, smg>>>(
        bufA, nullptr, nullptr, W_ego1, b_ego1, nullptr, yb0, N, 128, 128, invN);
    // ---- layer 1: GIN via linearity: y = x@W ; out = y + segsum(y) + b ----
    gemm_tc_kernel<2, false, false, false, false><<<g64, 256, smg>>>(
        nullptr, yb0, nullptr, W_gin1, nullptr, bufB, nullptr, N, OUTC, 64, 1.0f);
    segsum64f_kernel<<<sg, 256>>>(bufB, offE, adjE, bufA, N);
    // ---- fused add + bias + log_softmax ----
    final_logsoftmax_kernel<<<sg, 256>>>(bufB, bufA, b_gin1, (float*)d_out, N, OUTC);
}

// round 5
// speedup vs baseline: 2.1280x; 2.1280x over previous
#include <cuda_runtime.h>
#include <cuda_fp16.h>
#include <math.h>
#include <stdint.h>

#define F 128
#define MAXN 50000
#define MAXEGO 1250000
#define MAXE 700000
#define SCAN_TILE 1024
#define MAX_TILES 64

// fp32 scratch
__device__ float g_bufA[MAXN * F];
__device__ float g_bufB[MAXN * F];
// fp16 activation shadows
__device__ __half g_xb[MAXN * F];
__device__ __half g_yb0[MAXN * F];
__device__ __half g_yb1[MAXN * F];
// CSR scratch
__device__ int g_degEgo[MAXN];
__device__ int g_degE[MAXN];
__device__ int g_offEgo[MAXN + 1];
__device__ int g_offE[MAXN + 1];
__device__ int g_curEgo[MAXN];
__device__ int g_curE[MAXN];
__device__ int g_adjEgo[MAXEGO];
__device__ int g_adjE[MAXE];
__device__ int g_partEgo[MAX_TILES];
__device__ int g_partE[MAX_TILES];

// ---------------------------------------------------------------------------
__global__ void f2h_kernel(const float* __restrict__ x, __half* __restrict__ y, int n4) {
    int i = blockIdx.x * blockDim.x + threadIdx.x;
    if (i >= n4) return;
    float4 v = ((const float4*)x)[i];
    __half2 h0 = __floats2half2_rn(v.x, v.y);
    __half2 h1 = __floats2half2_rn(v.z, v.w);
    uint2 u;
    u.x = *(uint32_t*)&h0; u.y = *(uint32_t*)&h1;
    ((uint2*)y)[i] = u;
}

__global__ void hist_kernel(const int* __restrict__ w, int ne, int* __restrict__ deg) {
    int i = blockIdx.x * blockDim.x + threadIdx.x;
    if (i < ne) atomicAdd(&deg[__ldg(w + i)], 1);
}

// ---------------------------------------------------------------------------
// 3-phase exclusive scan over n ints (n <= MAX_TILES*SCAN_TILE)
// phase 1: per-tile sums. 256 thr, 4 elems/thr.
__global__ void scan_p1_kernel(const int* __restrict__ deg, int n, int* __restrict__ part) {
    __shared__ int ws[8];
    int b = blockIdx.x, t = threadIdx.x;
    int base = b * SCAN_TILE + t * 4;
    int s = 0;
#pragma unroll
    for (int j = 0; j < 4; j++) {
        int i = base + j;
        if (i < n) s += __ldg(deg + i);
    }
    int lane = t & 31, wid = t >> 5;
#pragma unroll
    for (int o = 16; o; o >>= 1) s += __shfl_down_sync(0xffffffffu, s, o);
    if (lane == 0) ws[wid] = s;
    __syncthreads();
    if (t < 8) {
        int v = ws[t];
#pragma unroll
        for (int o = 4; o; o >>= 1) v += __shfl_down_sync(0xffu, v, o);
        if (t == 0) part[b] = v;
    }
}

// phase 2: scan partials in place (exclusive), write total to off[n]. 1 block.
__global__ void scan_p2_kernel(int* __restrict__ part, int nb, int* __restrict__ off, int n) {
    int t = threadIdx.x;  // blockDim = 64 >= nb
    int v = (t < nb) ? part[t] : 0;
    int lane = t & 31, wid = t >> 5;
    __shared__ int ws[2];
    int x = v;
#pragma unroll
    for (int o = 1; o < 32; o <<= 1) {
        int u = __shfl_up_sync(0xffffffffu, x, o);
        if (lane >= o) x += u;
    }
    if (lane == 31) ws[wid] = x;
    __syncthreads();
    int incl = x + (wid ? ws[0] : 0);
    if (t < nb) part[t] = incl - v;  // exclusive
    if (t == nb - 1) off[n] = incl;  // total
}

// phase 3: per-tile exclusive scan + tile offset -> off, cur.
__global__ void scan_p3_kernel(const int* __restrict__ deg, int n,
                               const int* __restrict__ part,
                               int* __restrict__ off, int* __restrict__ cur) {
    __shared__ int ws[8];
    int b = blockIdx.x, t = threadIdx.x;
    int base = b * SCAN_TILE + t * 4;
    int v[4];
    int s = 0;
#pragma unroll
    for (int j = 0; j < 4; j++) {
        int i = base + j;
        v[j] = (i < n) ? __ldg(deg + i) : 0;
        s += v[j];
    }
    int lane = t & 31, wid = t >> 5;
    int x = s;
#pragma unroll
    for (int o = 1; o < 32; o <<= 1) {
        int u = __shfl_up_sync(0xffffffffu, x, o);
        if (lane >= o) x += u;
    }
    if (lane == 31) ws[wid] = x;
    __syncthreads();
    if (wid == 0) {
        int w = (lane < 8) ? ws[lane] : 0;
#pragma unroll
        for (int o = 1; o < 8; o <<= 1) {
            int u = __shfl_up_sync(0xffffffffu, w, o);
            if (lane >= o) w += u;
        }
        if (lane < 8) ws[lane] = w;
    }
    __syncthreads();
    int run = __ldg(part + b) + (x - s) + (wid ? ws[wid - 1] : 0);
#pragma unroll
    for (int j = 0; j < 4; j++) {
        int i = base + j;
        if (i < n) { off[i] = run; cur[i] = run; }
        run += v[j];
    }
}

__global__ void fill_kernel(const int* __restrict__ w, const int* __restrict__ r,
                            int ne, int* __restrict__ cur, int* __restrict__ adj) {
    int i = blockIdx.x * blockDim.x + threadIdx.x;
    if (i >= ne) return;
    int pos = atomicAdd(&cur[__ldg(w + i)], 1);
    adj[pos] = __ldg(r + i);
}

// ---------------------------------------------------------------------------
// segsum over CSR, fp16 source rows (128 wide) -> fp32 out. Warp per node.
__device__ __forceinline__ void addh2(float2& a, uint32_t h) {
    float2 f = __half22float2(*(__half2*)&h);
    a.x += f.x; a.y += f.y;
}
__global__ void segsum128h_kernel(const __half* __restrict__ x,
                                  const int* __restrict__ off,
                                  const int* __restrict__ adj,
                                  float* __restrict__ out, int n) {
    int gw = (blockIdx.x * blockDim.x + threadIdx.x) >> 5;
    int lane = threadIdx.x & 31;
    if (gw >= n) return;
    int s = __ldg(off + gw), e = __ldg(off + gw + 1);
    float2 acc[4] = {{0.f,0.f},{0.f,0.f},{0.f,0.f},{0.f,0.f}};
    for (int j = s; j < e; ) {
        int cnt = min(32, e - j);
        int my = (lane < cnt) ? __ldg(adj + j + lane) : 0;
        int k = 0;
        for (; k + 2 <= cnt; k += 2) {
            int r0 = __shfl_sync(0xffffffffu, my, k);
            int r1 = __shfl_sync(0xffffffffu, my, k + 1);
            uint4 u0 = __ldg((const uint4*)(x + (size_t)r0 * 128) + lane);
            uint4 u1 = __ldg((const uint4*)(x + (size_t)r1 * 128) + lane);
            addh2(acc[0], u0.x); addh2(acc[1], u0.y); addh2(acc[2], u0.z); addh2(acc[3], u0.w);
            addh2(acc[0], u1.x); addh2(acc[1], u1.y); addh2(acc[2], u1.z); addh2(acc[3], u1.w);
        }
        if (k < cnt) {
            int r0 = __shfl_sync(0xffffffffu, my, k);
            uint4 u0 = __ldg((const uint4*)(x + (size_t)r0 * 128) + lane);
            addh2(acc[0], u0.x); addh2(acc[1], u0.y); addh2(acc[2], u0.z); addh2(acc[3], u0.w);
        }
        j += cnt;
    }
    float4* op = (float4*)(out + (size_t)gw * 128 + lane * 8);
    op[0] = make_float4(acc[0].x, acc[0].y, acc[1].x, acc[1].y);
    op[1] = make_float4(acc[2].x, acc[2].y, acc[3].x, acc[3].y);
}

// segsum over CSR, fp32 source rows (64 wide) -> fp32. Warp per node.
__global__ void segsum64f_kernel(const float* __restrict__ x,
                                 const int* __restrict__ off,
                                 const int* __restrict__ adj,
                                 float* __restrict__ out, int n) {
    int gw = (blockIdx.x * blockDim.x + threadIdx.x) >> 5;
    int lane = threadIdx.x & 31;
    if (gw >= n) return;
    int s = __ldg(off + gw), e = __ldg(off + gw + 1);
    float2 acc = make_float2(0.f, 0.f);
    for (int j = s; j < e; ) {
        int cnt = min(32, e - j);
        int my = (lane < cnt) ? __ldg(adj + j + lane) : 0;
        int k = 0;
        for (; k + 2 <= cnt; k += 2) {
            int r0 = __shfl_sync(0xffffffffu, my, k);
            int r1 = __shfl_sync(0xffffffffu, my, k + 1);
            float2 v0 = __ldg((const float2*)(x + (size_t)r0 * 64) + lane);
            float2 v1 = __ldg((const float2*)(x + (size_t)r1 * 64) + lane);
            acc.x += v0.x + v1.x; acc.y += v0.y + v1.y;
        }
        if (k < cnt) {
            int r0 = __shfl_sync(0xffffffffu, my, k);
            float2 v0 = __ldg((const float2*)(x + (size_t)r0 * 64) + lane);
            acc.x += v0.x; acc.y += v0.y;
        }
        j += cnt;
    }
    *(float2*)(out + (size_t)gw * 64 + lane * 2) = acc;
}

// ---------------------------------------------------------------------------
// TF32 tensor-core GEMM, 64x64 tile per CTA (grid.y = col tile of 64).
// AMODE 0: A = scale * Af ; 1: A = Ah + B2f ; 2: A = Ah.
// BOUT: write fp16 (stride 128) else fp32 (stride ncstride).
__device__ __forceinline__ uint32_t f2tf32(float f) {
    uint32_t u;
    asm("cvt.rna.tf32.f32 %0, %1;" : "=r"(u) : "f"(f));
    return u;
}
__device__ __forceinline__ void mma_tf32(float& c0, float& c1, float& c2, float& c3,
                                         uint32_t a0, uint32_t a1, uint32_t a2, uint32_t a3,
                                         uint32_t b0, uint32_t b1) {
    asm volatile(
        "mma.sync.aligned.m16n8k8.row.col.f32.tf32.tf32.f32 "
        "{%0,%1,%2,%3}, {%4,%5,%6,%7}, {%8,%9}, {%0,%1,%2,%3};"
        : "+f"(c0), "+f"(c1), "+f"(c2), "+f"(c3)
        : "r"(a0), "r"(a1), "r"(a2), "r"(a3), "r"(b0), "r"(b1));
}

template <int AMODE, bool RELU, bool BIAS, bool VECW, bool BOUT>
__global__ void __launch_bounds__(256, 3)
gemm_tc_kernel(const float* __restrict__ Af, const __half* __restrict__ Ah,
               const float* __restrict__ B2f,
               const float* __restrict__ W, const float* __restrict__ bias,
               float* __restrict__ Cf, __half* __restrict__ Ch,
               int M, int nca, int ncstride, float scale) {
    constexpr int PW = 72;
    constexpr int PA = 132;

    extern __shared__ float sm[];
    uint32_t* Ws = (uint32_t*)sm;              // [128][72] tf32
    uint32_t* As = (uint32_t*)(sm + 128 * PW); // [64][132] tf32
    __shared__ float bs[64];

    const int tid  = threadIdx.x;
    const int lane = tid & 31;
    const int warp = tid >> 5;
    const int wr   = warp >> 1;
    const int wc   = warp & 1;
    const int g    = lane >> 2;
    const int t    = lane & 3;
    const int cb   = blockIdx.y * 64;

    if (VECW) {
#pragma unroll
        for (int i = tid; i < 128 * 16; i += 256) {
            int k = i >> 4, c4 = i & 15;
            float4 v = __ldg((const float4*)(W + (size_t)k * nca + cb) + c4);
            uint4 u;
            u.x = f2tf32(v.x); u.y = f2tf32(v.y); u.z = f2tf32(v.z); u.w = f2tf32(v.w);
            *(uint4*)(Ws + k * PW + c4 * 4) = u;
        }
    } else {
#pragma unroll
        for (int i = tid; i < 128 * 64; i += 256) {
            int k = i >> 6, c = i & 63;
            int gc = cb + c;
            float w = (gc < nca) ? __ldg(W + (size_t)k * nca + gc) : 0.f;
            Ws[k * PW + c] = f2tf32(w);
        }
    }
    if (BIAS && tid < 64) bs[tid] = (cb + tid < nca) ? bias[cb + tid] : 0.f;

    const int base = blockIdx.x * 64;
    if (AMODE == 0) {
#pragma unroll
        for (int i = tid; i < 64 * 32; i += 256) {
            int rr = i >> 5, c4 = i & 31;
            int row = base + rr;
            uint4 u = make_uint4(0u, 0u, 0u, 0u);
            if (row < M) {
                float4 v = ((const float4*)(Af + (size_t)row * 128))[c4];
                u.x = f2tf32(v.x * scale); u.y = f2tf32(v.y * scale);
                u.z = f2tf32(v.z * scale); u.w = f2tf32(v.w * scale);
            }
            ((uint4*)(As + rr * PA))[c4] = u;
        }
    } else {
#pragma unroll
        for (int i = tid; i < 64 * 16; i += 256) {
            int rr = i >> 4, c8 = i & 15;
            int row = base + rr;
            uint4 o0 = make_uint4(0u, 0u, 0u, 0u);
            uint4 o1 = make_uint4(0u, 0u, 0u, 0u);
            if (row < M) {
                uint4 hu = __ldg((const uint4*)(Ah + (size_t)row * 128) + c8);
                float2 f0 = __half22float2(*(__half2*)&hu.x);
                float2 f1 = __half22float2(*(__half2*)&hu.y);
                float2 f2 = __half22float2(*(__half2*)&hu.z);
                float2 f3 = __half22float2(*(__half2*)&hu.w);
                if (AMODE == 1) {
                    float4 b0 = ((const float4*)(B2f + (size_t)row * 128))[c8 * 2];
                    float4 b1 = ((const float4*)(B2f + (size_t)row * 128))[c8 * 2 + 1];
                    f0.x += b0.x; f0.y += b0.y; f1.x += b0.z; f1.y += b0.w;
                    f2.x += b1.x; f2.y += b1.y; f3.x += b1.z; f3.y += b1.w;
                }
                o0.x = f2tf32(f0.x); o0.y = f2tf32(f0.y);
                o0.z = f2tf32(f1.x); o0.w = f2tf32(f1.y);
                o1.x = f2tf32(f2.x); o1.y = f2tf32(f2.y);
                o1.z = f2tf32(f3.x); o1.w = f2tf32(f3.y);
            }
            uint4* dst = (uint4*)(As + rr * PA + c8 * 8);
            dst[0] = o0; dst[1] = o1;
        }
    }
    __syncthreads();

    float acc[4][4];
#pragma unroll
    for (int nt = 0; nt < 4; nt++)
#pragma unroll
        for (int j = 0; j < 4; j++) acc[nt][j] = 0.f;

    const int r0 = wr * 16 + g;
#pragma unroll
    for (int ks = 0; ks < 16; ks++) {
        const int k0 = ks * 8;
        uint32_t a0 = As[r0 * PA + k0 + t];
        uint32_t a1 = As[(r0 + 8) * PA + k0 + t];
        uint32_t a2 = As[r0 * PA + k0 + t + 4];
        uint32_t a3 = As[(r0 + 8) * PA + k0 + t + 4];
#pragma unroll
        for (int nt = 0; nt < 4; nt++) {
            int n = wc * 32 + nt * 8 + g;
            uint32_t b0 = Ws[(k0 + t) * PW + n];
            uint32_t b1 = Ws[(k0 + t + 4) * PW + n];
            mma_tf32(acc[nt][0], acc[nt][1], acc[nt][2], acc[nt][3],
                     a0, a1, a2, a3, b0, b1);
        }
    }

    int gr0 = base + wr * 16 + g;
    int gr1 = gr0 + 8;
#pragma unroll
    for (int nt = 0; nt < 4; nt++) {
        int col = wc * 32 + nt * 8 + t * 2;
        float bx = BIAS ? bs[col] : 0.f;
        float by = BIAS ? bs[col + 1] : 0.f;
        float2 v0 = make_float2(acc[nt][0] + bx, acc[nt][1] + by);
        float2 v1 = make_float2(acc[nt][2] + bx, acc[nt][3] + by);
        if (RELU) {
            v0.x = fmaxf(v0.x, 0.f); v0.y = fmaxf(v0.y, 0.f);
            v1.x = fmaxf(v1.x, 0.f); v1.y = fmaxf(v1.y, 0.f);
        }
        int gcol = cb + col;
        if (BOUT) {
            __half2 h0 = __floats2half2_rn(v0.x, v0.y);
            __half2 h1 = __floats2half2_rn(v1.x, v1.y);
            if (gr0 < M) *(__half2*)(Ch + (size_t)gr0 * 128 + gcol) = h0;
            if (gr1 < M) *(__half2*)(Ch + (size_t)gr1 * 128 + gcol) = h1;
        } else {
            if (gr0 < M) *(float2*)(Cf + (size_t)gr0 * ncstride + gcol) = v0;
            if (gr1 < M) *(float2*)(Cf + (size_t)gr1 * ncstride + gcol) = v1;
        }
    }
}

// ---------------------------------------------------------------------------
// out = log_softmax(y + aggr + bias) over nc=47 cols; y/aggr stride 64.
__global__ void final_logsoftmax_kernel(const float* __restrict__ y,
                                        const float* __restrict__ aggr,
                                        const float* __restrict__ bias,
                                        float* __restrict__ out, int M, int nc) {
    int warp = (blockIdx.x * blockDim.x + threadIdx.x) >> 5;
    int lane = threadIdx.x & 31;
    if (warp >= M) return;
    const float* yp = y + (size_t)warp * 64;
    const float* ap = aggr + (size_t)warp * 64;
    int c2 = lane + 32;
    float v1 = (lane < nc) ? yp[lane] + ap[lane] + __ldg(bias + lane) : -INFINITY;
    float v2 = (c2 < nc)   ? yp[c2] + ap[c2] + __ldg(bias + c2)       : -INFINITY;
    float mx = fmaxf(v1, v2);
#pragma unroll
    for (int o = 16; o; o >>= 1) mx = fmaxf(mx, __shfl_xor_sync(0xffffffffu, mx, o));
    float s = ((lane < nc) ? expf(v1 - mx) : 0.f) + ((c2 < nc) ? expf(v2 - mx) : 0.f);
#pragma unroll
    for (int o = 16; o; o >>= 1) s += __shfl_xor_sync(0xffffffffu, s, o);
    float lg = logf(s) + mx;
    float* orow = out + (size_t)warp * nc;
    if (lane < nc) orow[lane] = v1 - lg;
    if (c2 < nc)   orow[c2]   = v2 - lg;
}

// ---------------------------------------------------------------------------
extern "C" void kernel_launch(void* const* d_in, const int* in_sizes, int n_in,
                              void* d_out, int out_size) {
    const float* x_in   = (const float*)d_in[0];
    const int*   ei     = (const int*)d_in[1];
    const int*   ego    = (const int*)d_in[2];
    const float* W_ego0 = (const float*)d_in[3];
    const float* b_ego0 = (const float*)d_in[4];
    const float* W_gin0 = (const float*)d_in[5];
    const float* b_gin0 = (const float*)d_in[6];
    const float* W_ego1 = (const float*)d_in[7];
    const float* b_ego1 = (const float*)d_in[8];
    const float* W_gin1 = (const float*)d_in[9];
    const float* b_gin1 = (const float*)d_in[10];

    int N    = in_sizes[0] / F;
    int E    = in_sizes[1] / 2;
    int EGO  = in_sizes[2] / 2;
    int OUTC = in_sizes[10];
    float invN = 1.0f / (float)N;

    float *bufA, *bufB;
    __half *xb, *yb0, *yb1;
    int *degEgo, *degE, *offEgo, *offE, *curEgo, *curE, *adjEgo, *adjE, *partEgo, *partE;
    cudaGetSymbolAddress((void**)&bufA, g_bufA);
    cudaGetSymbolAddress((void**)&bufB, g_bufB);
    cudaGetSymbolAddress((void**)&xb, g_xb);
    cudaGetSymbolAddress((void**)&yb0, g_yb0);
    cudaGetSymbolAddress((void**)&yb1, g_yb1);
    cudaGetSymbolAddress((void**)&degEgo, g_degEgo);
    cudaGetSymbolAddress((void**)&degE, g_degE);
    cudaGetSymbolAddress((void**)&offEgo, g_offEgo);
    cudaGetSymbolAddress((void**)&offE, g_offE);
    cudaGetSymbolAddress((void**)&curEgo, g_curEgo);
    cudaGetSymbolAddress((void**)&curE, g_curE);
    cudaGetSymbolAddress((void**)&adjEgo, g_adjEgo);
    cudaGetSymbolAddress((void**)&adjE, g_adjE);
    cudaGetSymbolAddress((void**)&partEgo, g_partEgo);
    cudaGetSymbolAddress((void**)&partE, g_partE);

    const size_t smg = (size_t)(128 * 72 + 64 * 132) * 4;
    cudaFuncSetAttribute(gemm_tc_kernel<0, true, true, true, true>,
                         cudaFuncAttributeMaxDynamicSharedMemorySize, (int)smg);
    cudaFuncSetAttribute(gemm_tc_kernel<1, true, true, true, true>,
                         cudaFuncAttributeMaxDynamicSharedMemorySize, (int)smg);
    cudaFuncSetAttribute(gemm_tc_kernel<2, false, false, false, false>,
                         cudaFuncAttributeMaxDynamicSharedMemorySize, (int)smg);

    dim3 g128((N + 63) / 64, 2);
    dim3 g64((N + 63) / 64, 1);
    int sg = (N * 32 + 255) / 256;   // warp-per-node kernels
    int ntiles = (N + SCAN_TILE - 1) / SCAN_TILE;

    // ---- CSR build (both lists) + fp16 convert ----
    cudaMemsetAsync(degEgo, 0, N * sizeof(int), 0);
    cudaMemsetAsync(degE, 0, N * sizeof(int), 0);
    f2h_kernel<<<(N * F / 4 + 255) / 256, 256>>>(x_in, xb, N * F / 4);
    hist_kernel<<<(EGO + 255) / 256, 256>>>(ego, EGO, degEgo);          // widx = ego_row
    hist_kernel<<<(E + 255) / 256, 256>>>(ei + E, E, degE);             // widx = tgt
    scan_p1_kernel<<<ntiles, 256>>>(degEgo, N, partEgo);
    scan_p1_kernel<<<ntiles, 256>>>(degE, N, partE);
    scan_p2_kernel<<<1, 64>>>(partEgo, ntiles, offEgo, N);
    scan_p2_kernel<<<1, 64>>>(partE, ntiles, offE, N);
    scan_p3_kernel<<<ntiles, 256>>>(degEgo, N, partEgo, offEgo, curEgo);
    scan_p3_kernel<<<ntiles, 256>>>(degE, N, partE, offE, curE);
    fill_kernel<<<(EGO + 255) / 256, 256>>>(ego, ego + EGO, EGO, curEgo, adjEgo); // ridx = ego_col
    fill_kernel<<<(E + 255) / 256, 256>>>(ei + E, ei, E, curE, adjE);             // ridx = src

    // ---- layer 0: Ego ----
    segsum128h_kernel<<<sg, 256>>>(xb, offEgo, adjEgo, bufA, N);
    gemm_tc_kernel<0, true, true, true, true><<<g128, 256, smg>>>(
        bufA, nullptr, nullptr, W_ego0, b_ego0, nullptr, yb0, N, 128, 128, invN);
    // ---- layer 0: GIN ----
    segsum128h_kernel<<<sg, 256>>>(yb0, offE, adjE, bufB, N);
    gemm_tc_kernel<1, true, true, true, true><<<g128, 256, smg>>>(
        nullptr, yb0, bufB, W_gin0, b_gin0, nullptr, yb1, N, 128, 128, 1.0f);
    // ---- layer 1: Ego ----
    segsum128h_kernel<<<sg, 256>>>(yb1, offEgo, adjEgo, bufA, N);
    gemm_tc_kernel<0, true, true, true, true><<<g128, 256, smg>>>(
        bufA, nullptr, nullptr, W_ego1, b_ego1, nullptr, yb0, N, 128, 128, invN);
    // ---- layer 1: GIN via linearity: y = x@W ; out = y + segsum(y) + b ----
    gemm_tc_kernel<2, false, false, false, false><<<g64, 256, smg>>>(
        nullptr, yb0, nullptr, W_gin1, nullptr, bufB, nullptr, N, OUTC, 64, 1.0f);
    segsum64f_kernel<<<sg, 256>>>(bufB, offE, adjE, bufA, N);
    // ---- fused add + bias + log_softmax ----
    final_logsoftmax_kernel<<<sg, 256>>>(bufB, bufA, b_gin1, (float*)d_out, N, OUTC);
}

// round 6
// speedup vs baseline: 2.8191x; 1.3247x over previous
#include <cuda_runtime.h>
#include <cuda_fp16.h>
#include <math.h>
#include <stdint.h>

#define F 128
#define MAXN 50000
#define MAXEGO 1250000
#define MAXE 700000
#define SCAN_TILE 1024
#define MAX_TILES 64

// fp32 scratch
__device__ float g_bufA[MAXN * F];
__device__ float g_bufB[MAXN * F];
// fp16 activation shadows
__device__ __half g_xb[MAXN * F];
__device__ __half g_yb0[MAXN * F];
__device__ __half g_yb1[MAXN * F];
// CSR scratch (list 0 = ego, list 1 = gin edges); contiguous for fused kernels
__device__ int g_deg[2 * MAXN];
__device__ int g_off[2 * (MAXN + 1)];
__device__ int g_cur[2 * MAXN];
__device__ int g_adjEgo[MAXEGO];
__device__ int g_adjE[MAXE];
__device__ int g_part[2 * MAX_TILES];

// ---------------------------------------------------------------------------
__global__ void f2h_kernel(const float* __restrict__ x, __half* __restrict__ y, int n4) {
    int i = blockIdx.x * blockDim.x + threadIdx.x;
    if (i >= n4) return;
    float4 v = ((const float4*)x)[i];
    __half2 h0 = __floats2half2_rn(v.x, v.y);
    __half2 h1 = __floats2half2_rn(v.z, v.w);
    uint2 u;
    u.x = *(uint32_t*)&h0; u.y = *(uint32_t*)&h1;
    ((uint2*)y)[i] = u;
}

__global__ void hist2_kernel(const int* __restrict__ w0, int n0,
                             const int* __restrict__ w1, int n1,
                             int* __restrict__ deg0, int* __restrict__ deg1) {
    int i = blockIdx.x * blockDim.x + threadIdx.x;
    if (i < n0) atomicAdd(&deg0[__ldg(w0 + i)], 1);
    if (i < n1) atomicAdd(&deg1[__ldg(w1 + i)], 1);
}

// ---------------------------------------------------------------------------
// 3-phase exclusive scan, two lists via blockIdx.y / thread-halves.
__global__ void scan_p1_kernel(const int* __restrict__ deg, int n,
                               int* __restrict__ part, int ntiles) {
    __shared__ int ws[8];
    const int* d = deg + blockIdx.y * n;
    int* p = part + blockIdx.y * ntiles;
    int b = blockIdx.x, t = threadIdx.x;
    int base = b * SCAN_TILE + t * 4;
    int s = 0;
#pragma unroll
    for (int j = 0; j < 4; j++) {
        int i = base + j;
        if (i < n) s += __ldg(d + i);
    }
    int lane = t & 31, wid = t >> 5;
#pragma unroll
    for (int o = 16; o; o >>= 1) s += __shfl_down_sync(0xffffffffu, s, o);
    if (lane == 0) ws[wid] = s;
    __syncthreads();
    if (t < 8) {
        int v = ws[t];
#pragma unroll
        for (int o = 4; o; o >>= 1) v += __shfl_down_sync(0xffu, v, o);
        if (t == 0) p[b] = v;
    }
}

// dual scan of partials: 128 threads, halves handle list 0 / list 1.
__global__ void scan_p2_kernel(int* __restrict__ part, int nb,
                               int* __restrict__ off, int n, int ntiles) {
    int list = threadIdx.x >> 6;
    int t = threadIdx.x & 63;
    int* pp = part + list * ntiles;
    int* op = off + list * (n + 1);
    int v = (t < nb) ? pp[t] : 0;
    __shared__ int ws[4];
    int lane = t & 31, wid = t >> 5;
    int x = v;
#pragma unroll
    for (int o = 1; o < 32; o <<= 1) {
        int u = __shfl_up_sync(0xffffffffu, x, o);
        if (lane >= o) x += u;
    }
    if (lane == 31) ws[list * 2 + wid] = x;
    __syncthreads();
    int incl = x + (wid ? ws[list * 2] : 0);
    if (t < nb) pp[t] = incl - v;  // exclusive
    if (t == nb - 1) op[n] = incl; // total
}

__global__ void scan_p3_kernel(const int* __restrict__ deg, int n,
                               const int* __restrict__ part,
                               int* __restrict__ off, int* __restrict__ cur, int ntiles) {
    __shared__ int ws[8];
    const int* d = deg + blockIdx.y * n;
    const int* p = part + blockIdx.y * ntiles;
    int* of = off + blockIdx.y * (n + 1);
    int* cu = cur + blockIdx.y * n;
    int b = blockIdx.x, t = threadIdx.x;
    int base = b * SCAN_TILE + t * 4;
    int v[4];
    int s = 0;
#pragma unroll
    for (int j = 0; j < 4; j++) {
        int i = base + j;
        v[j] = (i < n) ? __ldg(d + i) : 0;
        s += v[j];
    }
    int lane = t & 31, wid = t >> 5;
    int x = s;
#pragma unroll
    for (int o = 1; o < 32; o <<= 1) {
        int u = __shfl_up_sync(0xffffffffu, x, o);
        if (lane >= o) x += u;
    }
    if (lane == 31) ws[wid] = x;
    __syncthreads();
    if (wid == 0) {
        int w = (lane < 8) ? ws[lane] : 0;
#pragma unroll
        for (int o = 1; o < 8; o <<= 1) {
            int u = __shfl_up_sync(0xffffffffu, w, o);
            if (lane >= o) w += u;
        }
        if (lane < 8) ws[lane] = w;
    }
    __syncthreads();
    int run = __ldg(p + b) + (x - s) + (wid ? ws[wid - 1] : 0);
#pragma unroll
    for (int j = 0; j < 4; j++) {
        int i = base + j;
        if (i < n) { of[i] = run; cu[i] = run; }
        run += v[j];
    }
}

__global__ void fill2_kernel(const int* __restrict__ w0, const int* __restrict__ r0, int n0,
                             const int* __restrict__ w1, const int* __restrict__ r1, int n1,
                             int* __restrict__ cur0, int* __restrict__ cur1,
                             int* __restrict__ adj0, int* __restrict__ adj1) {
    int i = blockIdx.x * blockDim.x + threadIdx.x;
    if (i < n0) {
        int pos = atomicAdd(&cur0[__ldg(w0 + i)], 1);
        adj0[pos] = __ldg(r0 + i);
    }
    if (i < n1) {
        int pos = atomicAdd(&cur1[__ldg(w1 + i)], 1);
        adj1[pos] = __ldg(r1 + i);
    }
}

// ---------------------------------------------------------------------------
// segsum over CSR, fp16 source rows (128 halfs = 256B) -> fp32 out. Warp/node.
// Each lane reads uint2 (4 halfs): 32 lanes x 8B = exactly one row.
__device__ __forceinline__ void addh2(float2& a, uint32_t h) {
    float2 f = __half22float2(*(__half2*)&h);
    a.x += f.x; a.y += f.y;
}
__global__ void segsum128h_kernel(const __half* __restrict__ x,
                                  const int* __restrict__ off,
                                  const int* __restrict__ adj,
                                  float* __restrict__ out, int n) {
    int gw = (blockIdx.x * blockDim.x + threadIdx.x) >> 5;
    int lane = threadIdx.x & 31;
    if (gw >= n) return;
    int s = __ldg(off + gw), e = __ldg(off + gw + 1);
    float2 acc0 = make_float2(0.f, 0.f), acc1 = make_float2(0.f, 0.f);
    for (int j = s; j < e; ) {
        int cnt = min(32, e - j);
        int my = (lane < cnt) ? __ldg(adj + j + lane) : 0;
        int k = 0;
        for (; k + 4 <= cnt; k += 4) {
            int r0 = __shfl_sync(0xffffffffu, my, k);
            int r1 = __shfl_sync(0xffffffffu, my, k + 1);
            int r2 = __shfl_sync(0xffffffffu, my, k + 2);
            int r3 = __shfl_sync(0xffffffffu, my, k + 3);
            uint2 u0 = __ldg((const uint2*)(x + (size_t)r0 * 128) + lane);
            uint2 u1 = __ldg((const uint2*)(x + (size_t)r1 * 128) + lane);
            uint2 u2 = __ldg((const uint2*)(x + (size_t)r2 * 128) + lane);
            uint2 u3 = __ldg((const uint2*)(x + (size_t)r3 * 128) + lane);
            addh2(acc0, u0.x); addh2(acc1, u0.y);
            addh2(acc0, u1.x); addh2(acc1, u1.y);
            addh2(acc0, u2.x); addh2(acc1, u2.y);
            addh2(acc0, u3.x); addh2(acc1, u3.y);
        }
        for (; k < cnt; k++) {
            int r0 = __shfl_sync(0xffffffffu, my, k);
            uint2 u0 = __ldg((const uint2*)(x + (size_t)r0 * 128) + lane);
            addh2(acc0, u0.x); addh2(acc1, u0.y);
        }
        j += cnt;
    }
    *(float4*)(out + (size_t)gw * 128 + lane * 4) =
        make_float4(acc0.x, acc0.y, acc1.x, acc1.y);
}

// segsum over CSR, fp32 source rows (64 wide = 256B) -> fp32. Warp per node.
__global__ void segsum64f_kernel(const float* __restrict__ x,
                                 const int* __restrict__ off,
                                 const int* __restrict__ adj,
                                 float* __restrict__ out, int n) {
    int gw = (blockIdx.x * blockDim.x + threadIdx.x) >> 5;
    int lane = threadIdx.x & 31;
    if (gw >= n) return;
    int s = __ldg(off + gw), e = __ldg(off + gw + 1);
    float2 acc = make_float2(0.f, 0.f);
    for (int j = s; j < e; ) {
        int cnt = min(32, e - j);
        int my = (lane < cnt) ? __ldg(adj + j + lane) : 0;
        int k = 0;
        for (; k + 2 <= cnt; k += 2) {
            int r0 = __shfl_sync(0xffffffffu, my, k);
            int r1 = __shfl_sync(0xffffffffu, my, k + 1);
            float2 v0 = __ldg((const float2*)(x + (size_t)r0 * 64) + lane);
            float2 v1 = __ldg((const float2*)(x + (size_t)r1 * 64) + lane);
            acc.x += v0.x + v1.x; acc.y += v0.y + v1.y;
        }
        if (k < cnt) {
            int r0 = __shfl_sync(0xffffffffu, my, k);
            float2 v0 = __ldg((const float2*)(x + (size_t)r0 * 64) + lane);
            acc.x += v0.x; acc.y += v0.y;
        }
        j += cnt;
    }
    *(float2*)(out + (size_t)gw * 64 + lane * 2) = acc;
}

// ---------------------------------------------------------------------------
// fp16 tensor-core GEMM (mma.m16n8k16), 64x64 tile per CTA, grid.y = col tile.
// AMODE 0: A = scale * Af ; 1: A = Ah + B2f ; 2: A = Ah.
// BOUT: write fp16 (stride 128) else fp32 (stride ncstride).
__device__ __forceinline__ void mma_f16(float& c0, float& c1, float& c2, float& c3,
                                        uint32_t a0, uint32_t a1, uint32_t a2, uint32_t a3,
                                        uint32_t b0, uint32_t b1) {
    asm volatile(
        "mma.sync.aligned.m16n8k16.row.col.f32.f16.f16.f32 "
        "{%0,%1,%2,%3}, {%4,%5,%6,%7}, {%8,%9}, {%0,%1,%2,%3};"
        : "+f"(c0), "+f"(c1), "+f"(c2), "+f"(c3)
        : "r"(a0), "r"(a1), "r"(a2), "r"(a3), "r"(b0), "r"(b1));
}

template <int AMODE, bool RELU, bool BIAS, bool VECW, bool BOUT>
__global__ void __launch_bounds__(256, 4)
gemm_h_kernel(const float* __restrict__ Af, const __half* __restrict__ Ah,
              const float* __restrict__ B2f,
              const float* __restrict__ W, const float* __restrict__ bias,
              float* __restrict__ Cf, __half* __restrict__ Ch,
              int M, int nca, int ncstride, float scale) {
    constexpr int PWH = 136;  // halfs per W row [n][k], pad for conflict-free frags
    constexpr int PAH = 136;  // halfs per A row [m][k]
    __shared__ __half Wt[64 * PWH];
    __shared__ __half As[64 * PAH];
    __shared__ float bs[64];

    const int tid  = threadIdx.x;
    const int lane = tid & 31;
    const int warp = tid >> 5;
    const int wr   = warp >> 1;   // 0..3 (16-row group)
    const int wc   = warp & 1;    // 0..1 (32-col group)
    const int g    = lane >> 2;   // 0..7
    const int t    = lane & 3;    // 0..3
    const int cb   = blockIdx.y * 64;

    // stage W transposed: Wt[n][k] (gmem reads coalesced along n)
    {
        int tn = tid & 63;
        int gc = cb + tn;
        for (int kb = (tid >> 6) * 8; kb < 128; kb += 32) {
            __half tmp[8];
#pragma unroll
            for (int j = 0; j < 8; j++) {
                int k = kb + j;
                float w;
                if (VECW) w = __ldg(W + (size_t)k * nca + gc);
                else      w = (gc < nca) ? __ldg(W + (size_t)k * nca + gc) : 0.f;
                tmp[j] = __float2half_rn(w);
            }
            *(uint4*)(Wt + tn * PWH + kb) = *(uint4*)tmp;
        }
    }
    if (BIAS && tid < 64) bs[tid] = (cb + tid < nca) ? bias[cb + tid] : 0.f;

    // stage A tile [64][128] halfs
    const int base = blockIdx.x * 64;
    if (AMODE == 2) {
#pragma unroll
        for (int u = tid; u < 64 * 16; u += 256) {
            int rr = u >> 4, c8 = u & 15;
            int row = base + rr;
            uint4 hv = make_uint4(0u, 0u, 0u, 0u);
            if (row < M) hv = __ldg((const uint4*)(Ah + (size_t)row * 128) + c8);
            *(uint4*)(As + rr * PAH + c8 * 8) = hv;
        }
    } else if (AMODE == 0) {
#pragma unroll
        for (int u = tid; u < 64 * 16; u += 256) {
            int rr = u >> 4, c8 = u & 15;
            int row = base + rr;
            uint4 o = make_uint4(0u, 0u, 0u, 0u);
            if (row < M) {
                const float4* ap = (const float4*)(Af + (size_t)row * 128) + c8 * 2;
                float4 v0 = ap[0], v1 = ap[1];
                __half2 h0 = __floats2half2_rn(v0.x * scale, v0.y * scale);
                __half2 h1 = __floats2half2_rn(v0.z * scale, v0.w * scale);
                __half2 h2 = __floats2half2_rn(v1.x * scale, v1.y * scale);
                __half2 h3 = __floats2half2_rn(v1.z * scale, v1.w * scale);
                o.x = *(uint32_t*)&h0; o.y = *(uint32_t*)&h1;
                o.z = *(uint32_t*)&h2; o.w = *(uint32_t*)&h3;
            }
            *(uint4*)(As + rr * PAH + c8 * 8) = o;
        }
    } else {  // AMODE 1: Ah + B2f
#pragma unroll
        for (int u = tid; u < 64 * 16; u += 256) {
            int rr = u >> 4, c8 = u & 15;
            int row = base + rr;
            uint4 o = make_uint4(0u, 0u, 0u, 0u);
            if (row < M) {
                uint4 hu = __ldg((const uint4*)(Ah + (size_t)row * 128) + c8);
                const float4* bp = (const float4*)(B2f + (size_t)row * 128) + c8 * 2;
                float4 b0 = bp[0], b1 = bp[1];
                float2 f0 = __half22float2(*(__half2*)&hu.x);
                float2 f1 = __half22float2(*(__half2*)&hu.y);
                float2 f2 = __half22float2(*(__half2*)&hu.z);
                float2 f3 = __half22float2(*(__half2*)&hu.w);
                __half2 h0 = __floats2half2_rn(f0.x + b0.x, f0.y + b0.y);
                __half2 h1 = __floats2half2_rn(f1.x + b0.z, f1.y + b0.w);
                __half2 h2 = __floats2half2_rn(f2.x + b1.x, f2.y + b1.y);
                __half2 h3 = __floats2half2_rn(f3.x + b1.z, f3.y + b1.w);
                o.x = *(uint32_t*)&h0; o.y = *(uint32_t*)&h1;
                o.z = *(uint32_t*)&h2; o.w = *(uint32_t*)&h3;
            }
            *(uint4*)(As + rr * PAH + c8 * 8) = o;
        }
    }
    __syncthreads();

    float acc[4][4];
#pragma unroll
    for (int nt = 0; nt < 4; nt++)
#pragma unroll
        for (int j = 0; j < 4; j++) acc[nt][j] = 0.f;

    const int r0 = wr * 16 + g;
    const __half* arow0 = As + r0 * PAH;
    const __half* arow1 = As + (r0 + 8) * PAH;
#pragma unroll
    for (int ks = 0; ks < 8; ks++) {
        const int k0 = ks * 16;
        uint32_t a0 = *(const uint32_t*)(arow0 + k0 + 2 * t);
        uint32_t a1 = *(const uint32_t*)(arow1 + k0 + 2 * t);
        uint32_t a2 = *(const uint32_t*)(arow0 + k0 + 2 * t + 8);
        uint32_t a3 = *(const uint32_t*)(arow1 + k0 + 2 * t + 8);
#pragma unroll
        for (int nt = 0; nt < 4; nt++) {
            int n = wc * 32 + nt * 8 + g;
            uint32_t b0 = *(const uint32_t*)(Wt + n * PWH + k0 + 2 * t);
            uint32_t b1 = *(const uint32_t*)(Wt + n * PWH + k0 + 2 * t + 8);
            mma_f16(acc[nt][0], acc[nt][1], acc[nt][2], acc[nt][3],
                    a0, a1, a2, a3, b0, b1);
        }
    }

    // epilogue: c0,c1 -> row r0 cols 2t,2t+1 ; c2,c3 -> row r0+8
    int gr0 = base + wr * 16 + g;
    int gr1 = gr0 + 8;
#pragma unroll
    for (int nt = 0; nt < 4; nt++) {
        int col = wc * 32 + nt * 8 + t * 2;
        float bx = BIAS ? bs[col] : 0.f;
        float by = BIAS ? bs[col + 1] : 0.f;
        float2 v0 = make_float2(acc[nt][0] + bx, acc[nt][1] + by);
        float2 v1 = make_float2(acc[nt][2] + bx, acc[nt][3] + by);
        if (RELU) {
            v0.x = fmaxf(v0.x, 0.f); v0.y = fmaxf(v0.y, 0.f);
            v1.x = fmaxf(v1.x, 0.f); v1.y = fmaxf(v1.y, 0.f);
        }
        int gcol = cb + col;
        if (BOUT) {
            __half2 h0 = __floats2half2_rn(v0.x, v0.y);
            __half2 h1 = __floats2half2_rn(v1.x, v1.y);
            if (gr0 < M) *(__half2*)(Ch + (size_t)gr0 * 128 + gcol) = h0;
            if (gr1 < M) *(__half2*)(Ch + (size_t)gr1 * 128 + gcol) = h1;
        } else {
            if (gr0 < M) *(float2*)(Cf + (size_t)gr0 * ncstride + gcol) = v0;
            if (gr1 < M) *(float2*)(Cf + (size_t)gr1 * ncstride + gcol) = v1;
        }
    }
}

// ---------------------------------------------------------------------------
// out = log_softmax(y + aggr + bias) over nc=47 cols; y/aggr stride 64.
__global__ void final_logsoftmax_kernel(const float* __restrict__ y,
                                        const float* __restrict__ aggr,
                                        const float* __restrict__ bias,
                                        float* __restrict__ out, int M, int nc) {
    int warp = (blockIdx.x * blockDim.x + threadIdx.x) >> 5;
    int lane = threadIdx.x & 31;
    if (warp >= M) return;
    const float* yp = y + (size_t)warp * 64;
    const float* ap = aggr + (size_t)warp * 64;
    int c2 = lane + 32;
    float v1 = (lane < nc) ? yp[lane] + ap[lane] + __ldg(bias + lane) : -INFINITY;
    float v2 = (c2 < nc)   ? yp[c2] + ap[c2] + __ldg(bias + c2)       : -INFINITY;
    float mx = fmaxf(v1, v2);
#pragma unroll
    for (int o = 16; o; o >>= 1) mx = fmaxf(mx, __shfl_xor_sync(0xffffffffu, mx, o));
    float s = ((lane < nc) ? expf(v1 - mx) : 0.f) + ((c2 < nc) ? expf(v2 - mx) : 0.f);
#pragma unroll
    for (int o = 16; o; o >>= 1) s += __shfl_xor_sync(0xffffffffu, s, o);
    float lg = logf(s) + mx;
    float* orow = out + (size_t)warp * nc;
    if (lane < nc) orow[lane] = v1 - lg;
    if (c2 < nc)   orow[c2]   = v2 - lg;
}

// ---------------------------------------------------------------------------
extern "C" void kernel_launch(void* const* d_in, const int* in_sizes, int n_in,
                              void* d_out, int out_size) {
    const float* x_in   = (const float*)d_in[0];
    const int*   ei     = (const int*)d_in[1];
    const int*   ego    = (const int*)d_in[2];
    const float* W_ego0 = (const float*)d_in[3];
    const float* b_ego0 = (const float*)d_in[4];
    const float* W_gin0 = (const float*)d_in[5];
    const float* b_gin0 = (const float*)d_in[6];
    const float* W_ego1 = (const float*)d_in[7];
    const float* b_ego1 = (const float*)d_in[8];
    const float* W_gin1 = (const float*)d_in[9];
    const float* b_gin1 = (const float*)d_in[10];

    int N    = in_sizes[0] / F;
    int E    = in_sizes[1] / 2;
    int EGO  = in_sizes[2] / 2;
    int OUTC = in_sizes[10];
    float invN = 1.0f / (float)N;

    float *bufA, *bufB;
    __half *xb, *yb0, *yb1;
    int *deg, *off, *cur, *adjEgo, *adjE, *part;
    cudaGetSymbolAddress((void**)&bufA, g_bufA);
    cudaGetSymbolAddress((void**)&bufB, g_bufB);
    cudaGetSymbolAddress((void**)&xb, g_xb);
    cudaGetSymbolAddress((void**)&yb0, g_yb0);
    cudaGetSymbolAddress((void**)&yb1, g_yb1);
    cudaGetSymbolAddress((void**)&deg, g_deg);
    cudaGetSymbolAddress((void**)&off, g_off);
    cudaGetSymbolAddress((void**)&cur, g_cur);
    cudaGetSymbolAddress((void**)&adjEgo, g_adjEgo);
    cudaGetSymbolAddress((void**)&adjE, g_adjE);
    cudaGetSymbolAddress((void**)&part, g_part);

    int *degEgo = deg,       *degE = deg + N;
    int *offEgo = off,       *offE = off + (N + 1);
    int *curEgo = cur,       *curE = cur + N;

    dim3 g128((N + 63) / 64, 2);
    dim3 g64((N + 63) / 64, 1);
    int sg = (N * 32 + 255) / 256;   // warp-per-node kernels
    int ntiles = (N + SCAN_TILE - 1) / SCAN_TILE;
    int maxE = (EGO > E) ? EGO : E;
    dim3 scang(ntiles, 2);

    // ---- CSR build (both lists) + fp16 convert : 7 launches ----
    cudaMemsetAsync(deg, 0, 2 * N * sizeof(int), 0);
    f2h_kernel<<<(N * F / 4 + 255) / 256, 256>>>(x_in, xb, N * F / 4);
    hist2_kernel<<<(maxE + 255) / 256, 256>>>(ego, EGO, ei + E, E, degEgo, degE);
    scan_p1_kernel<<<scang, 256>>>(deg, N, part, ntiles);
    scan_p2_kernel<<<1, 128>>>(part, ntiles, off, N, ntiles);
    scan_p3_kernel<<<scang, 256>>>(deg, N, part, off, cur, ntiles);
    fill2_kernel<<<(maxE + 255) / 256, 256>>>(ego, ego + EGO, EGO, ei + E, ei, E,
                                              curEgo, curE, adjEgo, adjE);

    // ---- layer 0: Ego ----
    segsum128h_kernel<<<sg, 256>>>(xb, offEgo, adjEgo, bufA, N);
    gemm_h_kernel<0, true, true, true, true><<<g128, 256>>>(
        bufA, nullptr, nullptr, W_ego0, b_ego0, nullptr, yb0, N, 128, 128, invN);
    // ---- layer 0: GIN ----
    segsum128h_kernel<<<sg, 256>>>(yb0, offE, adjE, bufB, N);
    gemm_h_kernel<1, true, true, true, true><<<g128, 256>>>(
        nullptr, yb0, bufB, W_gin0, b_gin0, nullptr, yb1, N, 128, 128, 1.0f);
    // ---- layer 1: Ego ----
    segsum128h_kernel<<<sg, 256>>>(yb1, offEgo, adjEgo, bufA, N);
    gemm_h_kernel<0, true, true, true, true><<<g128, 256>>>(
        bufA, nullptr, nullptr, W_ego1, b_ego1, nullptr, yb0, N, 128, 128, invN);
    // ---- layer 1: GIN via linearity: y = x@W ; out = y + segsum(y) + b ----
    gemm_h_kernel<2, false, false, false, false><<<g64, 256>>>(
        nullptr, yb0, nullptr, W_gin1, nullptr, bufB, nullptr, N, OUTC, 64, 1.0f);
    segsum64f_kernel<<<sg, 256>>>(bufB, offE, adjE, bufA, N);
    // ---- fused add + bias + log_softmax ----
    final_logsoftmax_kernel<<<sg, 256>>>(bufB, bufA, b_gin1, (float*)d_out, N, OUTC);
}